// round 5
// baseline (speedup 1.0000x reference)
#include <cuda_runtime.h>
#include <cuda_bf16.h>
#include <stdint.h>
#include <math.h>

#define Cdim 192
#define Dn 8
#define Hn 32
#define Wn 32
#define NHEAD 6
#define HDIM 32
#define HIDN 768
#define NTOK 8192
#define SCALE 0.17677669529663687f

typedef __nv_bfloat16 bf16;

// ---------------- scratch ----------------
__device__ float g_t[NTOK * Cdim];
__device__ float g_y[NTOK * Cdim];
__device__ float g_xt[Cdim * Dn * Hn * Wn];
__device__ float g_s[NTOK * Cdim];
__device__ bf16  g_qkvb[NTOK * 3 * Cdim];
__device__ bf16  g_yb[NTOK * Cdim];
__device__ bf16  g_ob[NTOK * Cdim];
__device__ bf16  g_hidb[NTOK * HIDN];
__device__ bf16  g_wb[884736];

#define OFF_TQKV 0
#define OFF_TOUT 110592
#define OFF_TFC1 147456
#define OFF_TFC2 294912
#define OFF_SQKV 442368
#define OFF_SPROJ 552960
#define OFF_SFC1 589824
#define OFF_SFC2 737280

__device__ __forceinline__ float warp_sum(float v) {
#pragma unroll
    for (int o = 16; o > 0; o >>= 1) v += __shfl_xor_sync(0xffffffffu, v, o);
    return v;
}
__device__ __forceinline__ float warp_max(float v) {
#pragma unroll
    for (int o = 16; o > 0; o >>= 1) v = fmaxf(v, __shfl_xor_sync(0xffffffffu, v, o));
    return v;
}

__device__ __forceinline__ void cp16(void* dst, const void* src) {
    unsigned d = (unsigned)__cvta_generic_to_shared(dst);
    asm volatile("cp.async.cg.shared.global [%0], [%1], 16;" :: "r"(d), "l"(src));
}

// ---------------- weight conversion ----------------
__global__ void convert_weights(const float* __restrict__ a0, const float* __restrict__ a1,
                                const float* __restrict__ a2, const float* __restrict__ a3,
                                const float* __restrict__ a4, const float* __restrict__ a5,
                                const float* __restrict__ a6, const float* __restrict__ a7) {
    int i = blockIdx.x * blockDim.x + threadIdx.x;
    const float* src; int off;
    if      (i < 110592) { src = a0; off = 0; }
    else if (i < 147456) { src = a1; off = 110592; }
    else if (i < 294912) { src = a2; off = 147456; }
    else if (i < 442368) { src = a3; off = 294912; }
    else if (i < 552960) { src = a4; off = 442368; }
    else if (i < 589824) { src = a5; off = 552960; }
    else if (i < 737280) { src = a6; off = 589824; }
    else                 { src = a7; off = 737280; }
    g_wb[i] = __float2bfloat16(src[i - off]);
}

// ---------------- build t = permute(x) + pos_emb ----------------
__global__ void build_t_kernel(const float* __restrict__ x, const float* __restrict__ pe) {
    int idx = blockIdx.x * blockDim.x + threadIdx.x;
    if (idx >= NTOK * Cdim) return;
    int r = idx / Cdim, c = idx % Cdim;
    int hw = r >> 3, s = r & 7;
    int h = hw >> 5, w = hw & 31;
    g_t[idx] = x[((c * Dn + s) * Hn + h) * Wn + w] + pe[s * Cdim + c];
}

// ---------------- LayerNorm ----------------
__global__ void ln_kernel(const float* __restrict__ in, const float* __restrict__ g,
                          const float* __restrict__ b, float* __restrict__ outf,
                          bf16* __restrict__ outb) {
    int warp = threadIdx.x >> 5, lane = threadIdx.x & 31;
    int r = blockIdx.x * 8 + warp;
    const float* row = in + (size_t)r * Cdim;
    float v[6];
    float s = 0.f;
#pragma unroll
    for (int i = 0; i < 6; i++) { v[i] = row[lane + 32 * i]; s += v[i]; }
    s = warp_sum(s);
    float m = s * (1.0f / Cdim);
    float var = 0.f;
#pragma unroll
    for (int i = 0; i < 6; i++) { float d = v[i] - m; var += d * d; }
    var = warp_sum(var) * (1.0f / Cdim);
    float rstd = rsqrtf(var + 1e-5f);
#pragma unroll
    for (int i = 0; i < 6; i++) {
        int c = lane + 32 * i;
        float o = (v[i] - m) * rstd * g[c] + b[c];
        if (outf) outf[(size_t)r * Cdim + c] = o;
        if (outb) outb[(size_t)r * Cdim + c] = __float2bfloat16(o);
    }
}

// ---------------- bf16 GEMM: BM=128, BN=64, BK=64, reg-pipelined ldmatrix ------
#define AST 72
#define BST 72
#define A_TILE (128 * AST)
#define B_TILE (64 * BST)
__global__ __launch_bounds__(256) void gemm_bf16(
    const bf16* __restrict__ A, const bf16* __restrict__ B,
    const float* __restrict__ bias, const float* __restrict__ res,
    float* __restrict__ outf, bf16* __restrict__ outb,
    int M, int N, int K, int act) {
    extern __shared__ bf16 sm[];
    bf16* As = sm;                       // [2][A_TILE]
    bf16* Bs = sm + 2 * A_TILE;          // [2][B_TILE]
    const int tid = threadIdx.x;
    const int lane = tid & 31;
    const int wid = tid >> 5;
    const int wm = wid >> 1, wn = wid & 1;
    const int row0 = blockIdx.y * 128, col0 = blockIdx.x * 64;
    const int gq = lane >> 2, tq = lane & 3;

    const int lrow8 = (lane & 7) + 8 * ((lane >> 3) & 1);
    const int lcol8 = 8 * (lane >> 4);
    unsigned as_base = (unsigned)__cvta_generic_to_shared(As);
    unsigned bs_base = (unsigned)__cvta_generic_to_shared(Bs);

    float acc[2][4][4] = {};

    auto load_tile = [&](int buf, int k0) {
#pragma unroll
        for (int i = 0; i < 4; i++) {
            int c = tid + i * 256;
            int m = c >> 3, kq = c & 7;
            cp16(&As[buf * A_TILE + m * AST + kq * 8],
                 &A[(size_t)(row0 + m) * K + k0 + kq * 8]);
        }
#pragma unroll
        for (int i = 0; i < 2; i++) {
            int c = tid + i * 256;
            int kr = c >> 3, nq = c & 7;
            cp16(&Bs[buf * B_TILE + kr * BST + nq * 8],
                 &B[(size_t)(k0 + kr) * N + col0 + nq * 8]);
        }
        asm volatile("cp.async.commit_group;");
    };

    unsigned af[2][2][4], bfr[2][4][2];
    auto load_frag = [&](int pb, unsigned abuf, unsigned bbuf, int ks) {
#pragma unroll
        for (int i = 0; i < 2; i++) {
            unsigned addr = abuf + (unsigned)(((wm * 32 + i * 16 + lrow8) * AST + ks * 16 + lcol8) * 2);
            asm volatile("ldmatrix.sync.aligned.m8n8.x4.shared.b16 {%0,%1,%2,%3}, [%4];"
                         : "=r"(af[pb][i][0]), "=r"(af[pb][i][1]),
                           "=r"(af[pb][i][2]), "=r"(af[pb][i][3])
                         : "r"(addr));
        }
#pragma unroll
        for (int jp = 0; jp < 2; jp++) {
            unsigned addr = bbuf + (unsigned)(((ks * 16 + lrow8) * BST + wn * 32 + jp * 16 + lcol8) * 2);
            asm volatile("ldmatrix.sync.aligned.m8n8.x4.trans.shared.b16 {%0,%1,%2,%3}, [%4];"
                         : "=r"(bfr[pb][jp * 2][0]), "=r"(bfr[pb][jp * 2][1]),
                           "=r"(bfr[pb][jp * 2 + 1][0]), "=r"(bfr[pb][jp * 2 + 1][1])
                         : "r"(addr));
        }
    };

    load_tile(0, 0);
    int nk = K / 64;
    int buf = 0;
    for (int it = 0; it < nk; it++) {
        asm volatile("cp.async.wait_group 0;");
        __syncthreads();
        if (it + 1 < nk) load_tile(buf ^ 1, (it + 1) * 64);

        unsigned abuf = as_base + buf * (A_TILE * 2);
        unsigned bbuf = bs_base + buf * (B_TILE * 2);
        load_frag(0, abuf, bbuf, 0);
#pragma unroll
        for (int ks = 0; ks < 4; ks++) {
            int pb = ks & 1;
            if (ks < 3) load_frag(pb ^ 1, abuf, bbuf, ks + 1);
#pragma unroll
            for (int i = 0; i < 2; i++)
#pragma unroll
                for (int j = 0; j < 4; j++) {
                    asm volatile(
                        "mma.sync.aligned.m16n8k16.row.col.f32.bf16.bf16.f32 "
                        "{%0,%1,%2,%3}, {%4,%5,%6,%7}, {%8,%9}, {%0,%1,%2,%3};"
                        : "+f"(acc[i][j][0]), "+f"(acc[i][j][1]),
                          "+f"(acc[i][j][2]), "+f"(acc[i][j][3])
                        : "r"(af[pb][i][0]), "r"(af[pb][i][1]),
                          "r"(af[pb][i][2]), "r"(af[pb][i][3]),
                          "r"(bfr[pb][j][0]), "r"(bfr[pb][j][1]));
                }
        }
        buf ^= 1;
        __syncthreads();
    }

#pragma unroll
    for (int i = 0; i < 2; i++) {
        int r = row0 + wm * 32 + i * 16 + gq;
#pragma unroll
        for (int j = 0; j < 4; j++) {
            int c = col0 + wn * 32 + j * 8 + 2 * tq;
            float v0 = acc[i][j][0], v1 = acc[i][j][1];
            float v2 = acc[i][j][2], v3 = acc[i][j][3];
            if (bias) {
                float b0 = bias[c], b1 = bias[c + 1];
                v0 += b0; v1 += b1; v2 += b0; v3 += b1;
            }
            if (act) {
                v0 = 0.5f * v0 * (1.0f + erff(v0 * 0.7071067811865476f));
                v1 = 0.5f * v1 * (1.0f + erff(v1 * 0.7071067811865476f));
                v2 = 0.5f * v2 * (1.0f + erff(v2 * 0.7071067811865476f));
                v3 = 0.5f * v3 * (1.0f + erff(v3 * 0.7071067811865476f));
            }
            if (res) {
                v0 += res[(size_t)r * N + c];
                v1 += res[(size_t)r * N + c + 1];
                v2 += res[(size_t)(r + 8) * N + c];
                v3 += res[(size_t)(r + 8) * N + c + 1];
            }
            if (outf) {
                outf[(size_t)r * N + c]           = v0;
                outf[(size_t)r * N + c + 1]       = v1;
                outf[(size_t)(r + 8) * N + c]     = v2;
                outf[(size_t)(r + 8) * N + c + 1] = v3;
            }
            if (outb) {
                outb[(size_t)r * N + c]           = __float2bfloat16(v0);
                outb[(size_t)r * N + c + 1]       = __float2bfloat16(v1);
                outb[(size_t)(r + 8) * N + c]     = __float2bfloat16(v2);
                outb[(size_t)(r + 8) * N + c + 1] = __float2bfloat16(v3);
            }
        }
    }
}

// ---------------- time attention (bf16 qkv) ----------------
__global__ void time_attn_kernel() {
    int n = blockIdx.x;
    int h = threadIdx.x >> 5, lane = threadIdx.x & 31;
    const bf16* base = g_qkvb + (size_t)n * 8 * (3 * Cdim);
    float kreg[8], vreg[8];
#pragma unroll
    for (int j = 0; j < 8; j++) {
        kreg[j] = (float)base[j * 576 + Cdim + h * 32 + lane];
        vreg[j] = (float)base[j * 576 + 2 * Cdim + h * 32 + lane];
    }
#pragma unroll
    for (int s = 0; s < 8; s++) {
        float qv = (float)base[s * 576 + h * 32 + lane];
        float sc[8];
#pragma unroll
        for (int j = 0; j < 8; j++) sc[j] = warp_sum(qv * kreg[j]) * SCALE;
        float mx = sc[0];
#pragma unroll
        for (int j = 1; j < 8; j++) mx = fmaxf(mx, sc[j]);
        float sum = 0.f, o = 0.f;
#pragma unroll
        for (int j = 0; j < 8; j++) {
            float p = __expf(sc[j] - mx);
            sum += p;
            o += p * vreg[j];
        }
        g_ob[(size_t)(n * 8 + s) * Cdim + h * 32 + lane] = __float2bfloat16(o / sum);
    }
}

// ---------------- NAT attention v2: lane=neighbor K-pass, lane=channel V-pass ----
__global__ void nat_attn_kernel(const float* __restrict__ rpb) {
    int f = blockIdx.x >> 5;
    int hh = blockIdx.x & 31;
    int h = threadIdx.x >> 5, lane = threadIdx.x & 31;
    __shared__ float sp[NHEAD][64];
    int sh0 = min(max(hh - 3, 0), 25);

    // per-lane neighbor decomposition (fixed per block)
    const int n1v = (lane + 32 < 49);
    const int a0 = lane / 7, b0 = lane - 7 * a0;
    const int a1 = (lane + 32) / 7, b1 = (lane + 32) - 7 * a1;
    const int ia0 = sh0 + a0, ia1 = n1v ? (sh0 + a1) : sh0;
    const float bias_h0 = rpb[h * 169 + (ia0 - hh + 6) * 13];   // + rw added later
    const float bias_h1 = n1v ? rpb[h * 169 + (ia1 - hh + 6) * 13] : 0.f;

    const bf16* qkvb = g_qkvb;
    const size_t frow = (size_t)f * 1024;

    for (int ww = 0; ww < 32; ww++) {
        size_t m = frow + hh * 32 + ww;
        int sw0 = min(max(ww - 3, 0), 25);
        float qd_own = (float)qkvb[m * 576 + h * 32 + lane] * SCALE;

        const bf16* k0p = qkvb + (frow + ia0 * 32 + sw0 + b0) * 576 + Cdim + h * 32;
        const bf16* k1p = qkvb + (frow + ia1 * 32 + sw0 + b1) * 576 + Cdim + h * 32;
        float s0 = 0.f, s1 = 0.f;
#pragma unroll
        for (int d = 0; d < 32; d++) {
            float qd = __shfl_sync(0xffffffffu, qd_own, d);
            s0 = fmaf(qd, (float)k0p[d], s0);
            s1 = fmaf(qd, (float)k1p[d], s1);
        }
        // add rel-pos bias: rpb[h][rh][rw], rw = sw0 + b - ww + 6
        s0 += rpb[h * 169 + (ia0 - hh + 6) * 13 + (sw0 + b0 - ww + 6)];
        float s1b = n1v ? (s1 + rpb[h * 169 + (ia1 - hh + 6) * 13 + (sw0 + b1 - ww + 6)]) : -1e30f;

        float mx = warp_max(fmaxf(s0, s1b));
        float e0 = __expf(s0 - mx);
        float e1 = n1v ? __expf(s1b - mx) : 0.f;
        float sum = warp_sum(e0 + e1);
        sp[h][lane] = e0;
        if (lane < 17) sp[h][lane + 32] = e1;
        __syncwarp();

        // V pass: lane = channel d
        const bf16* vbase = qkvb + (frow + sh0 * 32 + sw0) * 576 + 2 * Cdim + h * 32 + lane;
        float o = 0.f;
#pragma unroll
        for (int n = 0; n < 49; n++) {
            o = fmaf(sp[h][n], (float)vbase[((n / 7) * 32 + (n % 7)) * 576], o);
        }
        g_ob[m * Cdim + h * 32 + lane] = __float2bfloat16(o / sum);
        __syncwarp();
    }
    (void)bias_h0; (void)bias_h1;
}

// ---------------- x_after_time = x + lnf(t); build space-stream s --------------
__global__ void add_time_kernel(const float* __restrict__ x) {
    int idx = blockIdx.x * blockDim.x + threadIdx.x;
    if (idx >= Cdim * Dn * Hn * Wn) return;
    int w = idx & 31;
    int t1 = idx >> 5;
    int h = t1 & 31;
    int t2 = t1 >> 5;
    int s = t2 & 7;
    int c = t2 >> 3;
    float val = x[idx] + g_y[(size_t)((h * 32 + w) * 8 + s) * Cdim + c];
    g_xt[idx] = val;
    g_s[(size_t)(s * 1024 + h * 32 + w) * Cdim + c] = val;
}

// ---------------- out = x_after_time + permute(space stream) -------------------
__global__ void final_kernel(float* __restrict__ out) {
    int idx = blockIdx.x * blockDim.x + threadIdx.x;
    if (idx >= Cdim * Dn * Hn * Wn) return;
    int w = idx & 31;
    int t1 = idx >> 5;
    int h = t1 & 31;
    int t2 = t1 >> 5;
    int s = t2 & 7;
    int c = t2 >> 3;
    out[idx] = g_xt[idx] + g_s[(size_t)(s * 1024 + h * 32 + w) * Cdim + c];
}

extern "C" void kernel_launch(void* const* d_in, const int* in_sizes, int n_in,
                              void* d_out, int out_size) {
    const float* x        = (const float*)d_in[0];
    const float* pos_emb  = (const float*)d_in[1];
    const float* t_ln1_g  = (const float*)d_in[2];
    const float* t_ln1_b  = (const float*)d_in[3];
    const float* t_qkv_w  = (const float*)d_in[4];
    const float* t_out_w  = (const float*)d_in[5];
    const float* t_out_b  = (const float*)d_in[6];
    const float* t_ln2_g  = (const float*)d_in[7];
    const float* t_ln2_b  = (const float*)d_in[8];
    const float* t_fc1_w  = (const float*)d_in[9];
    const float* t_fc1_b  = (const float*)d_in[10];
    const float* t_fc2_w  = (const float*)d_in[11];
    const float* t_fc2_b  = (const float*)d_in[12];
    const float* t_lnf_g  = (const float*)d_in[13];
    const float* t_lnf_b  = (const float*)d_in[14];
    const float* s_ln1_g  = (const float*)d_in[15];
    const float* s_ln1_b  = (const float*)d_in[16];
    const float* s_qkv_w  = (const float*)d_in[17];
    const float* s_qkv_b  = (const float*)d_in[18];
    const float* s_rpb    = (const float*)d_in[19];
    const float* s_proj_w = (const float*)d_in[20];
    const float* s_proj_b = (const float*)d_in[21];
    const float* s_ln2_g  = (const float*)d_in[22];
    const float* s_ln2_b  = (const float*)d_in[23];
    const float* s_fc1_w  = (const float*)d_in[24];
    const float* s_fc1_b  = (const float*)d_in[25];
    const float* s_fc2_w  = (const float*)d_in[26];
    const float* s_fc2_b  = (const float*)d_in[27];
    float* out = (float*)d_out;

    float *p_t, *p_y, *p_s;
    bf16 *p_yb, *p_ob, *p_hidb, *p_wb, *p_qkvb;
    cudaGetSymbolAddress((void**)&p_t, g_t);
    cudaGetSymbolAddress((void**)&p_y, g_y);
    cudaGetSymbolAddress((void**)&p_s, g_s);
    cudaGetSymbolAddress((void**)&p_yb, g_yb);
    cudaGetSymbolAddress((void**)&p_ob, g_ob);
    cudaGetSymbolAddress((void**)&p_hidb, g_hidb);
    cudaGetSymbolAddress((void**)&p_wb, g_wb);
    cudaGetSymbolAddress((void**)&p_qkvb, g_qkvb);

    const int NEL = Cdim * Dn * Hn * Wn;
    const int SMEM = (2 * A_TILE + 2 * B_TILE) * (int)sizeof(bf16);
    cudaFuncSetAttribute(gemm_bf16, cudaFuncAttributeMaxDynamicSharedMemorySize, SMEM);

    convert_weights<<<884736 / 256, 256>>>(t_qkv_w, t_out_w, t_fc1_w, t_fc2_w,
                                           s_qkv_w, s_proj_w, s_fc1_w, s_fc2_w);
    build_t_kernel<<<(NTOK * Cdim + 255) / 256, 256>>>(x, pos_emb);

    // ======== time transformer ========
    ln_kernel<<<NTOK / 8, 256>>>(p_t, t_ln1_g, t_ln1_b, nullptr, p_yb);
    gemm_bf16<<<dim3(9, 64), 256, SMEM>>>(p_yb, p_wb + OFF_TQKV, nullptr, nullptr,
                                          nullptr, p_qkvb, NTOK, 576, Cdim, 0);
    time_attn_kernel<<<1024, 192>>>();
    gemm_bf16<<<dim3(3, 64), 256, SMEM>>>(p_ob, p_wb + OFF_TOUT, t_out_b, p_t,
                                          p_t, nullptr, NTOK, Cdim, Cdim, 0);
    ln_kernel<<<NTOK / 8, 256>>>(p_t, t_ln2_g, t_ln2_b, nullptr, p_yb);
    gemm_bf16<<<dim3(12, 64), 256, SMEM>>>(p_yb, p_wb + OFF_TFC1, t_fc1_b, nullptr,
                                           nullptr, p_hidb, NTOK, HIDN, Cdim, 1);
    gemm_bf16<<<dim3(3, 64), 256, SMEM>>>(p_hidb, p_wb + OFF_TFC2, t_fc2_b, p_t,
                                          p_t, nullptr, NTOK, Cdim, HIDN, 0);
    ln_kernel<<<NTOK / 8, 256>>>(p_t, t_lnf_g, t_lnf_b, p_y, nullptr);
    add_time_kernel<<<(NEL + 255) / 256, 256>>>(x);

    // ======== space transformer (NAT) ========
    ln_kernel<<<NTOK / 8, 256>>>(p_s, s_ln1_g, s_ln1_b, nullptr, p_yb);
    gemm_bf16<<<dim3(9, 64), 256, SMEM>>>(p_yb, p_wb + OFF_SQKV, s_qkv_b, nullptr,
                                          nullptr, p_qkvb, NTOK, 576, Cdim, 0);
    nat_attn_kernel<<<256, 192>>>(s_rpb);
    gemm_bf16<<<dim3(3, 64), 256, SMEM>>>(p_ob, p_wb + OFF_SPROJ, s_proj_b, p_s,
                                          p_s, nullptr, NTOK, Cdim, Cdim, 0);
    ln_kernel<<<NTOK / 8, 256>>>(p_s, s_ln2_g, s_ln2_b, nullptr, p_yb);
    gemm_bf16<<<dim3(12, 64), 256, SMEM>>>(p_yb, p_wb + OFF_SFC1, s_fc1_b, nullptr,
                                           nullptr, p_hidb, NTOK, HIDN, Cdim, 1);
    gemm_bf16<<<dim3(3, 64), 256, SMEM>>>(p_hidb, p_wb + OFF_SFC2, s_fc2_b, p_s,
                                          p_s, nullptr, NTOK, Cdim, HIDN, 0);
    final_kernel<<<(NEL + 255) / 256, 256>>>(out);
}

// round 6
// speedup vs baseline: 1.8208x; 1.8208x over previous
#include <cuda_runtime.h>
#include <cuda_bf16.h>
#include <stdint.h>
#include <math.h>

#define Cdim 192
#define Dn 8
#define Hn 32
#define Wn 32
#define NHEAD 6
#define HDIM 32
#define HIDN 768
#define NTOK 8192
#define SCALE 0.17677669529663687f

typedef __nv_bfloat16 bf16;

// ---------------- scratch ----------------
__device__ float g_t[NTOK * Cdim];
__device__ float g_y[NTOK * Cdim];
__device__ float g_qkv[NTOK * 3 * Cdim];
__device__ float g_xt[Cdim * Dn * Hn * Wn];
__device__ float g_s[NTOK * Cdim];
__device__ bf16  g_yb[NTOK * Cdim];
__device__ bf16  g_ob[NTOK * Cdim];
__device__ bf16  g_hidb[NTOK * HIDN];
__device__ bf16  g_wb[884736];

#define OFF_TQKV 0
#define OFF_TOUT 110592
#define OFF_TFC1 147456
#define OFF_TFC2 294912
#define OFF_SQKV 442368
#define OFF_SPROJ 552960
#define OFF_SFC1 589824
#define OFF_SFC2 737280

__device__ __forceinline__ float warp_sum(float v) {
#pragma unroll
    for (int o = 16; o > 0; o >>= 1) v += __shfl_xor_sync(0xffffffffu, v, o);
    return v;
}

__device__ __forceinline__ void cp16(void* dst, const void* src) {
    unsigned d = (unsigned)__cvta_generic_to_shared(dst);
    asm volatile("cp.async.cg.shared.global [%0], [%1], 16;" :: "r"(d), "l"(src));
}

// ---------------- weight conversion ----------------
__global__ void convert_weights(const float* __restrict__ a0, const float* __restrict__ a1,
                                const float* __restrict__ a2, const float* __restrict__ a3,
                                const float* __restrict__ a4, const float* __restrict__ a5,
                                const float* __restrict__ a6, const float* __restrict__ a7) {
    int i = blockIdx.x * blockDim.x + threadIdx.x;
    const float* src; int off;
    if      (i < 110592) { src = a0; off = 0; }
    else if (i < 147456) { src = a1; off = 110592; }
    else if (i < 294912) { src = a2; off = 147456; }
    else if (i < 442368) { src = a3; off = 294912; }
    else if (i < 552960) { src = a4; off = 442368; }
    else if (i < 589824) { src = a5; off = 552960; }
    else if (i < 737280) { src = a6; off = 589824; }
    else                 { src = a7; off = 737280; }
    g_wb[i] = __float2bfloat16(src[i - off]);
}

// ---------------- build t = permute(x) + pos_emb ----------------
__global__ void build_t_kernel(const float* __restrict__ x, const float* __restrict__ pe) {
    int idx = blockIdx.x * blockDim.x + threadIdx.x;
    if (idx >= NTOK * Cdim) return;
    int r = idx / Cdim, c = idx % Cdim;
    int hw = r >> 3, s = r & 7;
    int h = hw >> 5, w = hw & 31;
    g_t[idx] = x[((c * Dn + s) * Hn + h) * Wn + w] + pe[s * Cdim + c];
}

// ---------------- LayerNorm ----------------
__global__ void ln_kernel(const float* __restrict__ in, const float* __restrict__ g,
                          const float* __restrict__ b, float* __restrict__ outf,
                          bf16* __restrict__ outb) {
    int warp = threadIdx.x >> 5, lane = threadIdx.x & 31;
    int r = blockIdx.x * 8 + warp;
    const float* row = in + (size_t)r * Cdim;
    float v[6];
    float s = 0.f;
#pragma unroll
    for (int i = 0; i < 6; i++) { v[i] = row[lane + 32 * i]; s += v[i]; }
    s = warp_sum(s);
    float m = s * (1.0f / Cdim);
    float var = 0.f;
#pragma unroll
    for (int i = 0; i < 6; i++) { float d = v[i] - m; var += d * d; }
    var = warp_sum(var) * (1.0f / Cdim);
    float rstd = rsqrtf(var + 1e-5f);
#pragma unroll
    for (int i = 0; i < 6; i++) {
        int c = lane + 32 * i;
        float o = (v[i] - m) * rstd * g[c] + b[c];
        if (outf) outf[(size_t)r * Cdim + c] = o;
        if (outb) outb[(size_t)r * Cdim + c] = __float2bfloat16(o);
    }
}

// ---------------- bf16 GEMM: BM=128, BN=64, BK=32, 3-stage cp.async ring -------
#define AST 40
#define BST 72
#define A_TILE (128 * AST)
#define B_TILE (32 * BST)
__global__ __launch_bounds__(256) void gemm_bf16(
    const bf16* __restrict__ A, const bf16* __restrict__ B,
    const float* __restrict__ bias, const float* __restrict__ res,
    float* __restrict__ outf, bf16* __restrict__ outb,
    int M, int N, int K, int act) {
    __shared__ bf16 As[3][A_TILE];
    __shared__ bf16 Bs[3][B_TILE];
    const int tid = threadIdx.x;
    const int lane = tid & 31;
    const int wid = tid >> 5;
    const int wm = wid >> 1, wn = wid & 1;
    const int row0 = blockIdx.y * 128, col0 = blockIdx.x * 64;
    const int gq = lane >> 2, tq = lane & 3;

    const int lrow8 = (lane & 7) + 8 * ((lane >> 3) & 1);
    const int lcol8 = 8 * (lane >> 4);
    unsigned as_base = (unsigned)__cvta_generic_to_shared(&As[0][0]);
    unsigned bs_base = (unsigned)__cvta_generic_to_shared(&Bs[0][0]);

    float acc[2][4][4] = {};

    const int a_m = (tid >> 2), a_q = (tid & 3);
    const int b_k = (tid >> 3), b_q = (tid & 7);

    auto load_tile = [&](int buf, int k0) {
#pragma unroll
        for (int j = 0; j < 2; j++) {
            int m = a_m + j * 64;
            cp16(&As[buf][m * AST + a_q * 8], &A[(size_t)(row0 + m) * K + k0 + a_q * 8]);
        }
        cp16(&Bs[buf][b_k * BST + b_q * 8], &B[(size_t)(k0 + b_k) * N + col0 + b_q * 8]);
        asm volatile("cp.async.commit_group;");
    };

    const int nk = K / 32;
    load_tile(0, 0);
    if (nk > 1) load_tile(1, 32);

    for (int it = 0; it < nk; it++) {
        if (it + 1 < nk) asm volatile("cp.async.wait_group 1;");
        else             asm volatile("cp.async.wait_group 0;");
        __syncthreads();
        if (it + 2 < nk) load_tile((it + 2) % 3, (it + 2) * 32);

        int buf = it % 3;
        unsigned abuf = as_base + buf * (A_TILE * 2);
        unsigned bbuf = bs_base + buf * (B_TILE * 2);
#pragma unroll
        for (int ks = 0; ks < 32; ks += 16) {
            unsigned af[2][4], bfr[4][2];
#pragma unroll
            for (int i = 0; i < 2; i++) {
                unsigned addr = abuf + (unsigned)(((wm * 32 + i * 16 + lrow8) * AST + ks + lcol8) * 2);
                asm volatile("ldmatrix.sync.aligned.m8n8.x4.shared.b16 {%0,%1,%2,%3}, [%4];"
                             : "=r"(af[i][0]), "=r"(af[i][1]), "=r"(af[i][2]), "=r"(af[i][3])
                             : "r"(addr));
            }
#pragma unroll
            for (int jp = 0; jp < 2; jp++) {
                unsigned addr = bbuf + (unsigned)(((ks + lrow8) * BST + wn * 32 + jp * 16 + lcol8) * 2);
                asm volatile("ldmatrix.sync.aligned.m8n8.x4.trans.shared.b16 {%0,%1,%2,%3}, [%4];"
                             : "=r"(bfr[jp * 2][0]), "=r"(bfr[jp * 2][1]),
                               "=r"(bfr[jp * 2 + 1][0]), "=r"(bfr[jp * 2 + 1][1])
                             : "r"(addr));
            }
#pragma unroll
            for (int i = 0; i < 2; i++)
#pragma unroll
                for (int j = 0; j < 4; j++) {
                    asm volatile(
                        "mma.sync.aligned.m16n8k16.row.col.f32.bf16.bf16.f32 "
                        "{%0,%1,%2,%3}, {%4,%5,%6,%7}, {%8,%9}, {%0,%1,%2,%3};"
                        : "+f"(acc[i][j][0]), "+f"(acc[i][j][1]),
                          "+f"(acc[i][j][2]), "+f"(acc[i][j][3])
                        : "r"(af[i][0]), "r"(af[i][1]), "r"(af[i][2]), "r"(af[i][3]),
                          "r"(bfr[j][0]), "r"(bfr[j][1]));
                }
        }
    }

    // epilogue
#pragma unroll
    for (int i = 0; i < 2; i++) {
        int r = row0 + wm * 32 + i * 16 + gq;
#pragma unroll
        for (int j = 0; j < 4; j++) {
            int c = col0 + wn * 32 + j * 8 + 2 * tq;
            float v0 = acc[i][j][0], v1 = acc[i][j][1];
            float v2 = acc[i][j][2], v3 = acc[i][j][3];
            if (bias) {
                float b0 = bias[c], b1 = bias[c + 1];
                v0 += b0; v1 += b1; v2 += b0; v3 += b1;
            }
            if (act) {
                v0 = 0.5f * v0 * (1.0f + erff(v0 * 0.7071067811865476f));
                v1 = 0.5f * v1 * (1.0f + erff(v1 * 0.7071067811865476f));
                v2 = 0.5f * v2 * (1.0f + erff(v2 * 0.7071067811865476f));
                v3 = 0.5f * v3 * (1.0f + erff(v3 * 0.7071067811865476f));
            }
            if (res) {
                v0 += res[(size_t)r * N + c];
                v1 += res[(size_t)r * N + c + 1];
                v2 += res[(size_t)(r + 8) * N + c];
                v3 += res[(size_t)(r + 8) * N + c + 1];
            }
            if (outf) {
                outf[(size_t)r * N + c]           = v0;
                outf[(size_t)r * N + c + 1]       = v1;
                outf[(size_t)(r + 8) * N + c]     = v2;
                outf[(size_t)(r + 8) * N + c + 1] = v3;
            }
            if (outb) {
                outb[(size_t)r * N + c]           = __float2bfloat16(v0);
                outb[(size_t)r * N + c + 1]       = __float2bfloat16(v1);
                outb[(size_t)(r + 8) * N + c]     = __float2bfloat16(v2);
                outb[(size_t)(r + 8) * N + c + 1] = __float2bfloat16(v3);
            }
        }
    }
}

// ---------------- time attention ----------------
__global__ void time_attn_kernel() {
    int n = blockIdx.x;
    int h = threadIdx.x >> 5, lane = threadIdx.x & 31;
    const float* base = g_qkv + (size_t)n * 8 * (3 * Cdim);
    float kreg[8], vreg[8];
#pragma unroll
    for (int j = 0; j < 8; j++) {
        kreg[j] = base[j * 576 + Cdim + h * 32 + lane];
        vreg[j] = base[j * 576 + 2 * Cdim + h * 32 + lane];
    }
#pragma unroll
    for (int s = 0; s < 8; s++) {
        float qv = base[s * 576 + h * 32 + lane];
        float sc[8];
#pragma unroll
        for (int j = 0; j < 8; j++) sc[j] = warp_sum(qv * kreg[j]) * SCALE;
        float mx = sc[0];
#pragma unroll
        for (int j = 1; j < 8; j++) mx = fmaxf(mx, sc[j]);
        float sum = 0.f, o = 0.f;
#pragma unroll
        for (int j = 0; j < 8; j++) {
            float p = __expf(sc[j] - mx);
            sum += p;
            o += p * vreg[j];
        }
        g_ob[(size_t)(n * 8 + s) * Cdim + h * 32 + lane] = __float2bfloat16(o / sum);
    }
}

// ---------------- NAT attention (round-4 proven version) ----------------
__global__ void nat_attn_kernel(const float* __restrict__ rpb) {
    int f = blockIdx.x >> 5;
    int hh = blockIdx.x & 31;
    int h = threadIdx.x >> 5, lane = threadIdx.x & 31;
    __shared__ float sc[NHEAD][52];
    int sh0 = min(max(hh - 3, 0), 25);
    for (int ww = 0; ww < 32; ww++) {
        int m = f * 1024 + hh * 32 + ww;
        float qv = g_qkv[(size_t)m * 576 + h * 32 + lane] * SCALE;
        int sw0 = min(max(ww - 3, 0), 25);
#pragma unroll
        for (int a = 0; a < 7; a++) {
            int ia = sh0 + a;
            int rh = ia - hh + 6;
            const float* krow = g_qkv + (size_t)(f * 1024 + ia * 32 + sw0) * 576 + Cdim + h * 32 + lane;
#pragma unroll
            for (int b = 0; b < 7; b++) {
                float d = warp_sum(qv * krow[b * 576]);
                if (lane == 0) {
                    int rw = sw0 + b - ww + 6;
                    sc[h][a * 7 + b] = d + rpb[h * 169 + rh * 13 + rw];
                }
            }
        }
        __syncwarp();
        float mx = -1e30f;
#pragma unroll
        for (int n2 = 0; n2 < 49; n2++) mx = fmaxf(mx, sc[h][n2]);
        float sum = 0.f, o = 0.f;
#pragma unroll
        for (int a = 0; a < 7; a++) {
            int ia = sh0 + a;
            const float* vrow = g_qkv + (size_t)(f * 1024 + ia * 32 + sw0) * 576 + 2 * Cdim + h * 32 + lane;
#pragma unroll
            for (int b = 0; b < 7; b++) {
                float p = __expf(sc[h][a * 7 + b] - mx);
                sum += p;
                o += p * vrow[b * 576];
            }
        }
        g_ob[(size_t)m * Cdim + h * 32 + lane] = __float2bfloat16(o / sum);
        __syncwarp();
    }
}

// ---------------- x_after_time = x + lnf(t); build space-stream s --------------
__global__ void add_time_kernel(const float* __restrict__ x) {
    int idx = blockIdx.x * blockDim.x + threadIdx.x;
    if (idx >= Cdim * Dn * Hn * Wn) return;
    int w = idx & 31;
    int t1 = idx >> 5;
    int h = t1 & 31;
    int t2 = t1 >> 5;
    int s = t2 & 7;
    int c = t2 >> 3;
    float val = x[idx] + g_y[(size_t)((h * 32 + w) * 8 + s) * Cdim + c];
    g_xt[idx] = val;
    g_s[(size_t)(s * 1024 + h * 32 + w) * Cdim + c] = val;
}

// ---------------- out = x_after_time + permute(space stream) -------------------
__global__ void final_kernel(float* __restrict__ out) {
    int idx = blockIdx.x * blockDim.x + threadIdx.x;
    if (idx >= Cdim * Dn * Hn * Wn) return;
    int w = idx & 31;
    int t1 = idx >> 5;
    int h = t1 & 31;
    int t2 = t1 >> 5;
    int s = t2 & 7;
    int c = t2 >> 3;
    out[idx] = g_xt[idx] + g_s[(size_t)(s * 1024 + h * 32 + w) * Cdim + c];
}

extern "C" void kernel_launch(void* const* d_in, const int* in_sizes, int n_in,
                              void* d_out, int out_size) {
    const float* x        = (const float*)d_in[0];
    const float* pos_emb  = (const float*)d_in[1];
    const float* t_ln1_g  = (const float*)d_in[2];
    const float* t_ln1_b  = (const float*)d_in[3];
    const float* t_qkv_w  = (const float*)d_in[4];
    const float* t_out_w  = (const float*)d_in[5];
    const float* t_out_b  = (const float*)d_in[6];
    const float* t_ln2_g  = (const float*)d_in[7];
    const float* t_ln2_b  = (const float*)d_in[8];
    const float* t_fc1_w  = (const float*)d_in[9];
    const float* t_fc1_b  = (const float*)d_in[10];
    const float* t_fc2_w  = (const float*)d_in[11];
    const float* t_fc2_b  = (const float*)d_in[12];
    const float* t_lnf_g  = (const float*)d_in[13];
    const float* t_lnf_b  = (const float*)d_in[14];
    const float* s_ln1_g  = (const float*)d_in[15];
    const float* s_ln1_b  = (const float*)d_in[16];
    const float* s_qkv_w  = (const float*)d_in[17];
    const float* s_qkv_b  = (const float*)d_in[18];
    const float* s_rpb    = (const float*)d_in[19];
    const float* s_proj_w = (const float*)d_in[20];
    const float* s_proj_b = (const float*)d_in[21];
    const float* s_ln2_g  = (const float*)d_in[22];
    const float* s_ln2_b  = (const float*)d_in[23];
    const float* s_fc1_w  = (const float*)d_in[24];
    const float* s_fc1_b  = (const float*)d_in[25];
    const float* s_fc2_w  = (const float*)d_in[26];
    const float* s_fc2_b  = (const float*)d_in[27];
    float* out = (float*)d_out;

    float *p_t, *p_y, *p_qkv, *p_s;
    bf16 *p_yb, *p_ob, *p_hidb, *p_wb;
    cudaGetSymbolAddress((void**)&p_t, g_t);
    cudaGetSymbolAddress((void**)&p_y, g_y);
    cudaGetSymbolAddress((void**)&p_qkv, g_qkv);
    cudaGetSymbolAddress((void**)&p_s, g_s);
    cudaGetSymbolAddress((void**)&p_yb, g_yb);
    cudaGetSymbolAddress((void**)&p_ob, g_ob);
    cudaGetSymbolAddress((void**)&p_hidb, g_hidb);
    cudaGetSymbolAddress((void**)&p_wb, g_wb);

    const int NEL = Cdim * Dn * Hn * Wn;

    convert_weights<<<884736 / 256, 256>>>(t_qkv_w, t_out_w, t_fc1_w, t_fc2_w,
                                           s_qkv_w, s_proj_w, s_fc1_w, s_fc2_w);
    build_t_kernel<<<(NTOK * Cdim + 255) / 256, 256>>>(x, pos_emb);

    // ======== time transformer ========
    ln_kernel<<<NTOK / 8, 256>>>(p_t, t_ln1_g, t_ln1_b, nullptr, p_yb);
    gemm_bf16<<<dim3(9, 64), 256>>>(p_yb, p_wb + OFF_TQKV, nullptr, nullptr,
                                    p_qkv, nullptr, NTOK, 576, Cdim, 0);
    time_attn_kernel<<<1024, 192>>>();
    gemm_bf16<<<dim3(3, 64), 256>>>(p_ob, p_wb + OFF_TOUT, t_out_b, p_t,
                                    p_t, nullptr, NTOK, Cdim, Cdim, 0);
    ln_kernel<<<NTOK / 8, 256>>>(p_t, t_ln2_g, t_ln2_b, nullptr, p_yb);
    gemm_bf16<<<dim3(12, 64), 256>>>(p_yb, p_wb + OFF_TFC1, t_fc1_b, nullptr,
                                     nullptr, p_hidb, NTOK, HIDN, Cdim, 1);
    gemm_bf16<<<dim3(3, 64), 256>>>(p_hidb, p_wb + OFF_TFC2, t_fc2_b, p_t,
                                    p_t, nullptr, NTOK, Cdim, HIDN, 0);
    ln_kernel<<<NTOK / 8, 256>>>(p_t, t_lnf_g, t_lnf_b, p_y, nullptr);
    add_time_kernel<<<(NEL + 255) / 256, 256>>>(x);

    // ======== space transformer (NAT) ========
    ln_kernel<<<NTOK / 8, 256>>>(p_s, s_ln1_g, s_ln1_b, nullptr, p_yb);
    gemm_bf16<<<dim3(9, 64), 256>>>(p_yb, p_wb + OFF_SQKV, s_qkv_b, nullptr,
                                    p_qkv, nullptr, NTOK, 576, Cdim, 0);
    nat_attn_kernel<<<256, 192>>>(s_rpb);
    gemm_bf16<<<dim3(3, 64), 256>>>(p_ob, p_wb + OFF_SPROJ, s_proj_b, p_s,
                                    p_s, nullptr, NTOK, Cdim, Cdim, 0);
    ln_kernel<<<NTOK / 8, 256>>>(p_s, s_ln2_g, s_ln2_b, nullptr, p_yb);
    gemm_bf16<<<dim3(12, 64), 256>>>(p_yb, p_wb + OFF_SFC1, s_fc1_b, nullptr,
                                     nullptr, p_hidb, NTOK, HIDN, Cdim, 1);
    gemm_bf16<<<dim3(3, 64), 256>>>(p_hidb, p_wb + OFF_SFC2, s_fc2_b, p_s,
                                    p_s, nullptr, NTOK, Cdim, HIDN, 0);
    final_kernel<<<(NEL + 255) / 256, 256>>>(out);
}

// round 7
// speedup vs baseline: 1.8662x; 1.0250x over previous
#include <cuda_runtime.h>
#include <cuda_bf16.h>
#include <stdint.h>
#include <math.h>

#define Cdim 192
#define Dn 8
#define Hn 32
#define Wn 32
#define NHEAD 6
#define HDIM 32
#define HIDN 768
#define NTOK 8192
#define SCALE 0.17677669529663687f

typedef __nv_bfloat16 bf16;

// ---------------- scratch ----------------
__device__ float g_t[NTOK * Cdim];
__device__ float g_y[NTOK * Cdim];
__device__ float g_qkv[NTOK * 3 * Cdim];
__device__ float g_xt[Cdim * Dn * Hn * Wn];
__device__ float g_s[NTOK * Cdim];
__device__ bf16  g_yb[NTOK * Cdim];
__device__ bf16  g_ob[NTOK * Cdim];
__device__ bf16  g_hidb[NTOK * HIDN];
__device__ bf16  g_wb[884736];

#define OFF_TQKV 0
#define OFF_TOUT 110592
#define OFF_TFC1 147456
#define OFF_TFC2 294912
#define OFF_SQKV 442368
#define OFF_SPROJ 552960
#define OFF_SFC1 589824
#define OFF_SFC2 737280

__device__ __forceinline__ float warp_sum(float v) {
#pragma unroll
    for (int o = 16; o > 0; o >>= 1) v += __shfl_xor_sync(0xffffffffu, v, o);
    return v;
}

__device__ __forceinline__ void cp16(void* dst, const void* src) {
    unsigned d = (unsigned)__cvta_generic_to_shared(dst);
    asm volatile("cp.async.cg.shared.global [%0], [%1], 16;" :: "r"(d), "l"(src));
}

__device__ __forceinline__ float gelu_f(float v) {
    return 0.5f * v * (1.0f + erff(v * 0.7071067811865476f));
}

// ---------------- weight conversion ----------------
__global__ void convert_weights(const float* __restrict__ a0, const float* __restrict__ a1,
                                const float* __restrict__ a2, const float* __restrict__ a3,
                                const float* __restrict__ a4, const float* __restrict__ a5,
                                const float* __restrict__ a6, const float* __restrict__ a7) {
    int i = blockIdx.x * blockDim.x + threadIdx.x;
    const float* src; int off;
    if      (i < 110592) { src = a0; off = 0; }
    else if (i < 147456) { src = a1; off = 110592; }
    else if (i < 294912) { src = a2; off = 147456; }
    else if (i < 442368) { src = a3; off = 294912; }
    else if (i < 552960) { src = a4; off = 442368; }
    else if (i < 589824) { src = a5; off = 552960; }
    else if (i < 737280) { src = a6; off = 589824; }
    else                 { src = a7; off = 737280; }
    g_wb[i] = __float2bfloat16(src[i - off]);
}

// ---------------- build t = permute(x) + pos_emb ----------------
__global__ void build_t_kernel(const float* __restrict__ x, const float* __restrict__ pe) {
    int idx = blockIdx.x * blockDim.x + threadIdx.x;
    if (idx >= NTOK * Cdim) return;
    int r = idx / Cdim, c = idx % Cdim;
    int hw = r >> 3, s = r & 7;
    int h = hw >> 5, w = hw & 31;
    g_t[idx] = x[((c * Dn + s) * Hn + h) * Wn + w] + pe[s * Cdim + c];
}

// ---------------- LayerNorm ----------------
__global__ void ln_kernel(const float* __restrict__ in, const float* __restrict__ g,
                          const float* __restrict__ b, float* __restrict__ outf,
                          bf16* __restrict__ outb) {
    int warp = threadIdx.x >> 5, lane = threadIdx.x & 31;
    int r = blockIdx.x * 8 + warp;
    const float* row = in + (size_t)r * Cdim;
    float v[6];
    float s = 0.f;
#pragma unroll
    for (int i = 0; i < 6; i++) { v[i] = row[lane + 32 * i]; s += v[i]; }
    s = warp_sum(s);
    float m = s * (1.0f / Cdim);
    float var = 0.f;
#pragma unroll
    for (int i = 0; i < 6; i++) { float d = v[i] - m; var += d * d; }
    var = warp_sum(var) * (1.0f / Cdim);
    float rstd = rsqrtf(var + 1e-5f);
#pragma unroll
    for (int i = 0; i < 6; i++) {
        int c = lane + 32 * i;
        float o = (v[i] - m) * rstd * g[c] + b[c];
        if (outf) outf[(size_t)r * Cdim + c] = o;
        if (outb) outb[(size_t)r * Cdim + c] = __float2bfloat16(o);
    }
}

#define AST 40
#define BST 72

// ============ wide GEMM: BM=128, BN=64, BK=32, 3-stage ring, reg-pipelined ======
#define A_TILE (128 * AST)
#define B_TILE (32 * BST)
__global__ __launch_bounds__(256) void gemm_bf16(
    const bf16* __restrict__ A, const bf16* __restrict__ B,
    const float* __restrict__ bias, const float* __restrict__ res,
    float* __restrict__ outf, bf16* __restrict__ outb,
    int M, int N, int K, int act) {
    __shared__ bf16 As[3][A_TILE];
    __shared__ bf16 Bs[3][B_TILE];
    const int tid = threadIdx.x;
    const int lane = tid & 31;
    const int wid = tid >> 5;
    const int wm = wid >> 1, wn = wid & 1;
    const int row0 = blockIdx.y * 128, col0 = blockIdx.x * 64;
    const int gq = lane >> 2, tq = lane & 3;

    const int lrow8 = (lane & 7) + 8 * ((lane >> 3) & 1);
    const int lcol8 = 8 * (lane >> 4);
    unsigned as_base = (unsigned)__cvta_generic_to_shared(&As[0][0]);
    unsigned bs_base = (unsigned)__cvta_generic_to_shared(&Bs[0][0]);

    float acc[2][4][4] = {};

    const int a_m = (tid >> 2), a_q = (tid & 3);
    const int b_k = (tid >> 3), b_q = (tid & 7);

    auto load_tile = [&](int buf, int k0) {
#pragma unroll
        for (int j = 0; j < 2; j++) {
            int m = a_m + j * 64;
            cp16(&As[buf][m * AST + a_q * 8], &A[(size_t)(row0 + m) * K + k0 + a_q * 8]);
        }
        cp16(&Bs[buf][b_k * BST + b_q * 8], &B[(size_t)(k0 + b_k) * N + col0 + b_q * 8]);
        asm volatile("cp.async.commit_group;");
    };

    unsigned af[2][2][4], bfr[2][4][2];
    auto load_frag = [&](int pb, unsigned abuf, unsigned bbuf, int ks) {
#pragma unroll
        for (int i = 0; i < 2; i++) {
            unsigned addr = abuf + (unsigned)(((wm * 32 + i * 16 + lrow8) * AST + ks + lcol8) * 2);
            asm volatile("ldmatrix.sync.aligned.m8n8.x4.shared.b16 {%0,%1,%2,%3}, [%4];"
                         : "=r"(af[pb][i][0]), "=r"(af[pb][i][1]),
                           "=r"(af[pb][i][2]), "=r"(af[pb][i][3])
                         : "r"(addr));
        }
#pragma unroll
        for (int jp = 0; jp < 2; jp++) {
            unsigned addr = bbuf + (unsigned)(((ks + lrow8) * BST + wn * 32 + jp * 16 + lcol8) * 2);
            asm volatile("ldmatrix.sync.aligned.m8n8.x4.trans.shared.b16 {%0,%1,%2,%3}, [%4];"
                         : "=r"(bfr[pb][jp * 2][0]), "=r"(bfr[pb][jp * 2][1]),
                           "=r"(bfr[pb][jp * 2 + 1][0]), "=r"(bfr[pb][jp * 2 + 1][1])
                         : "r"(addr));
        }
    };

    const int nk = K / 32;
    load_tile(0, 0);
    if (nk > 1) load_tile(1, 32);

    for (int it = 0; it < nk; it++) {
        if (it + 1 < nk) asm volatile("cp.async.wait_group 1;");
        else             asm volatile("cp.async.wait_group 0;");
        __syncthreads();
        if (it + 2 < nk) load_tile((it + 2) % 3, (it + 2) * 32);

        int buf = it % 3;
        unsigned abuf = as_base + buf * (A_TILE * 2);
        unsigned bbuf = bs_base + buf * (B_TILE * 2);
        load_frag(0, abuf, bbuf, 0);
#pragma unroll
        for (int ks = 0; ks < 2; ks++) {
            int pb = ks & 1;
            if (ks < 1) load_frag(pb ^ 1, abuf, bbuf, 16);
#pragma unroll
            for (int i = 0; i < 2; i++)
#pragma unroll
                for (int j = 0; j < 4; j++) {
                    asm volatile(
                        "mma.sync.aligned.m16n8k16.row.col.f32.bf16.bf16.f32 "
                        "{%0,%1,%2,%3}, {%4,%5,%6,%7}, {%8,%9}, {%0,%1,%2,%3};"
                        : "+f"(acc[i][j][0]), "+f"(acc[i][j][1]),
                          "+f"(acc[i][j][2]), "+f"(acc[i][j][3])
                        : "r"(af[pb][i][0]), "r"(af[pb][i][1]),
                          "r"(af[pb][i][2]), "r"(af[pb][i][3]),
                          "r"(bfr[pb][j][0]), "r"(bfr[pb][j][1]));
                }
        }
    }

#pragma unroll
    for (int i = 0; i < 2; i++) {
        int r = row0 + wm * 32 + i * 16 + gq;
#pragma unroll
        for (int j = 0; j < 4; j++) {
            int c = col0 + wn * 32 + j * 8 + 2 * tq;
            float v0 = acc[i][j][0], v1 = acc[i][j][1];
            float v2 = acc[i][j][2], v3 = acc[i][j][3];
            if (bias) {
                float b0 = bias[c], b1 = bias[c + 1];
                v0 += b0; v1 += b1; v2 += b0; v3 += b1;
            }
            if (act) { v0 = gelu_f(v0); v1 = gelu_f(v1); v2 = gelu_f(v2); v3 = gelu_f(v3); }
            if (res) {
                v0 += res[(size_t)r * N + c];
                v1 += res[(size_t)r * N + c + 1];
                v2 += res[(size_t)(r + 8) * N + c];
                v3 += res[(size_t)(r + 8) * N + c + 1];
            }
            if (outf) {
                outf[(size_t)r * N + c]           = v0;
                outf[(size_t)r * N + c + 1]       = v1;
                outf[(size_t)(r + 8) * N + c]     = v2;
                outf[(size_t)(r + 8) * N + c + 1] = v3;
            }
            if (outb) {
                outb[(size_t)r * N + c]           = __float2bfloat16(v0);
                outb[(size_t)r * N + c + 1]       = __float2bfloat16(v1);
                outb[(size_t)(r + 8) * N + c]     = __float2bfloat16(v2);
                outb[(size_t)(r + 8) * N + c + 1] = __float2bfloat16(v3);
            }
        }
    }
}

// ============ skinny GEMM: BM=64, BN=64, BK=32, 4 warps (for N=192 GEMMs) =======
#define A_TILE_S (64 * AST)
#define B_TILE_S (32 * BST)
__global__ __launch_bounds__(128) void gemm_bf16_s(
    const bf16* __restrict__ A, const bf16* __restrict__ B,
    const float* __restrict__ bias, const float* __restrict__ res,
    float* __restrict__ outf, bf16* __restrict__ outb,
    int M, int N, int K, int act) {
    __shared__ bf16 As[3][A_TILE_S];
    __shared__ bf16 Bs[3][B_TILE_S];
    const int tid = threadIdx.x;
    const int lane = tid & 31;
    const int wid = tid >> 5;
    const int wm = wid >> 1, wn = wid & 1;
    const int row0 = blockIdx.y * 64, col0 = blockIdx.x * 64;
    const int gq = lane >> 2, tq = lane & 3;

    const int lrow8 = (lane & 7) + 8 * ((lane >> 3) & 1);
    const int lcol8 = 8 * (lane >> 4);
    unsigned as_base = (unsigned)__cvta_generic_to_shared(&As[0][0]);
    unsigned bs_base = (unsigned)__cvta_generic_to_shared(&Bs[0][0]);

    float acc[2][4][4] = {};

    const int a_m = (tid >> 2), a_q = (tid & 3);   // 32 rows per pass, 2 passes
    const int b_k = (tid >> 3), b_q = (tid & 7);   // 16 rows per pass, 2 passes

    auto load_tile = [&](int buf, int k0) {
#pragma unroll
        for (int j = 0; j < 2; j++) {
            int m = a_m + j * 32;
            cp16(&As[buf][m * AST + a_q * 8], &A[(size_t)(row0 + m) * K + k0 + a_q * 8]);
        }
#pragma unroll
        for (int j = 0; j < 2; j++) {
            int kr = b_k + j * 16;
            cp16(&Bs[buf][kr * BST + b_q * 8], &B[(size_t)(k0 + kr) * N + col0 + b_q * 8]);
        }
        asm volatile("cp.async.commit_group;");
    };

    unsigned af[2][2][4], bfr[2][4][2];
    auto load_frag = [&](int pb, unsigned abuf, unsigned bbuf, int ks) {
#pragma unroll
        for (int i = 0; i < 2; i++) {
            unsigned addr = abuf + (unsigned)(((wm * 32 + i * 16 + lrow8) * AST + ks + lcol8) * 2);
            asm volatile("ldmatrix.sync.aligned.m8n8.x4.shared.b16 {%0,%1,%2,%3}, [%4];"
                         : "=r"(af[pb][i][0]), "=r"(af[pb][i][1]),
                           "=r"(af[pb][i][2]), "=r"(af[pb][i][3])
                         : "r"(addr));
        }
#pragma unroll
        for (int jp = 0; jp < 2; jp++) {
            unsigned addr = bbuf + (unsigned)(((ks + lrow8) * BST + wn * 32 + jp * 16 + lcol8) * 2);
            asm volatile("ldmatrix.sync.aligned.m8n8.x4.trans.shared.b16 {%0,%1,%2,%3}, [%4];"
                         : "=r"(bfr[pb][jp * 2][0]), "=r"(bfr[pb][jp * 2][1]),
                           "=r"(bfr[pb][jp * 2 + 1][0]), "=r"(bfr[pb][jp * 2 + 1][1])
                         : "r"(addr));
        }
    };

    const int nk = K / 32;
    load_tile(0, 0);
    if (nk > 1) load_tile(1, 32);

    for (int it = 0; it < nk; it++) {
        if (it + 1 < nk) asm volatile("cp.async.wait_group 1;");
        else             asm volatile("cp.async.wait_group 0;");
        __syncthreads();
        if (it + 2 < nk) load_tile((it + 2) % 3, (it + 2) * 32);

        int buf = it % 3;
        unsigned abuf = as_base + buf * (A_TILE_S * 2);
        unsigned bbuf = bs_base + buf * (B_TILE_S * 2);
        load_frag(0, abuf, bbuf, 0);
#pragma unroll
        for (int ks = 0; ks < 2; ks++) {
            int pb = ks & 1;
            if (ks < 1) load_frag(pb ^ 1, abuf, bbuf, 16);
#pragma unroll
            for (int i = 0; i < 2; i++)
#pragma unroll
                for (int j = 0; j < 4; j++) {
                    asm volatile(
                        "mma.sync.aligned.m16n8k16.row.col.f32.bf16.bf16.f32 "
                        "{%0,%1,%2,%3}, {%4,%5,%6,%7}, {%8,%9}, {%0,%1,%2,%3};"
                        : "+f"(acc[i][j][0]), "+f"(acc[i][j][1]),
                          "+f"(acc[i][j][2]), "+f"(acc[i][j][3])
                        : "r"(af[pb][i][0]), "r"(af[pb][i][1]),
                          "r"(af[pb][i][2]), "r"(af[pb][i][3]),
                          "r"(bfr[pb][j][0]), "r"(bfr[pb][j][1]));
                }
        }
    }

#pragma unroll
    for (int i = 0; i < 2; i++) {
        int r = row0 + wm * 32 + i * 16 + gq;
#pragma unroll
        for (int j = 0; j < 4; j++) {
            int c = col0 + wn * 32 + j * 8 + 2 * tq;
            float v0 = acc[i][j][0], v1 = acc[i][j][1];
            float v2 = acc[i][j][2], v3 = acc[i][j][3];
            if (bias) {
                float b0 = bias[c], b1 = bias[c + 1];
                v0 += b0; v1 += b1; v2 += b0; v3 += b1;
            }
            if (act) { v0 = gelu_f(v0); v1 = gelu_f(v1); v2 = gelu_f(v2); v3 = gelu_f(v3); }
            if (res) {
                v0 += res[(size_t)r * N + c];
                v1 += res[(size_t)r * N + c + 1];
                v2 += res[(size_t)(r + 8) * N + c];
                v3 += res[(size_t)(r + 8) * N + c + 1];
            }
            if (outf) {
                outf[(size_t)r * N + c]           = v0;
                outf[(size_t)r * N + c + 1]       = v1;
                outf[(size_t)(r + 8) * N + c]     = v2;
                outf[(size_t)(r + 8) * N + c + 1] = v3;
            }
            if (outb) {
                outb[(size_t)r * N + c]           = __float2bfloat16(v0);
                outb[(size_t)r * N + c + 1]       = __float2bfloat16(v1);
                outb[(size_t)(r + 8) * N + c]     = __float2bfloat16(v2);
                outb[(size_t)(r + 8) * N + c + 1] = __float2bfloat16(v3);
            }
        }
    }
}

// ---------------- time attention ----------------
__global__ void time_attn_kernel() {
    int n = blockIdx.x;
    int h = threadIdx.x >> 5, lane = threadIdx.x & 31;
    const float* base = g_qkv + (size_t)n * 8 * (3 * Cdim);
    float kreg[8], vreg[8];
#pragma unroll
    for (int j = 0; j < 8; j++) {
        kreg[j] = base[j * 576 + Cdim + h * 32 + lane];
        vreg[j] = base[j * 576 + 2 * Cdim + h * 32 + lane];
    }
#pragma unroll
    for (int s = 0; s < 8; s++) {
        float qv = base[s * 576 + h * 32 + lane];
        float sc[8];
#pragma unroll
        for (int j = 0; j < 8; j++) sc[j] = warp_sum(qv * kreg[j]) * SCALE;
        float mx = sc[0];
#pragma unroll
        for (int j = 1; j < 8; j++) mx = fmaxf(mx, sc[j]);
        float sum = 0.f, o = 0.f;
#pragma unroll
        for (int j = 0; j < 8; j++) {
            float p = __expf(sc[j] - mx);
            sum += p;
            o += p * vreg[j];
        }
        g_ob[(size_t)(n * 8 + s) * Cdim + h * 32 + lane] = __float2bfloat16(o / sum);
    }
}

// ---------------- NAT attention ----------------
__global__ void nat_attn_kernel(const float* __restrict__ rpb) {
    int f = blockIdx.x >> 5;
    int hh = blockIdx.x & 31;
    int h = threadIdx.x >> 5, lane = threadIdx.x & 31;
    __shared__ float sc[NHEAD][52];
    int sh0 = min(max(hh - 3, 0), 25);
    for (int ww = 0; ww < 32; ww++) {
        int m = f * 1024 + hh * 32 + ww;
        float qv = g_qkv[(size_t)m * 576 + h * 32 + lane] * SCALE;
        int sw0 = min(max(ww - 3, 0), 25);
#pragma unroll
        for (int a = 0; a < 7; a++) {
            int ia = sh0 + a;
            int rh = ia - hh + 6;
            const float* krow = g_qkv + (size_t)(f * 1024 + ia * 32 + sw0) * 576 + Cdim + h * 32 + lane;
#pragma unroll
            for (int b = 0; b < 7; b++) {
                float d = warp_sum(qv * krow[b * 576]);
                if (lane == 0) {
                    int rw = sw0 + b - ww + 6;
                    sc[h][a * 7 + b] = d + rpb[h * 169 + rh * 13 + rw];
                }
            }
        }
        __syncwarp();
        float mx = -1e30f;
#pragma unroll
        for (int n2 = 0; n2 < 49; n2++) mx = fmaxf(mx, sc[h][n2]);
        float sum = 0.f, o = 0.f;
#pragma unroll
        for (int a = 0; a < 7; a++) {
            int ia = sh0 + a;
            const float* vrow = g_qkv + (size_t)(f * 1024 + ia * 32 + sw0) * 576 + 2 * Cdim + h * 32 + lane;
#pragma unroll
            for (int b = 0; b < 7; b++) {
                float p = __expf(sc[h][a * 7 + b] - mx);
                sum += p;
                o += p * vrow[b * 576];
            }
        }
        g_ob[(size_t)m * Cdim + h * 32 + lane] = __float2bfloat16(o / sum);
        __syncwarp();
    }
}

// ---------------- x_after_time = x + lnf(t); build space-stream s --------------
__global__ void add_time_kernel(const float* __restrict__ x) {
    int idx = blockIdx.x * blockDim.x + threadIdx.x;
    if (idx >= Cdim * Dn * Hn * Wn) return;
    int w = idx & 31;
    int t1 = idx >> 5;
    int h = t1 & 31;
    int t2 = t1 >> 5;
    int s = t2 & 7;
    int c = t2 >> 3;
    float val = x[idx] + g_y[(size_t)((h * 32 + w) * 8 + s) * Cdim + c];
    g_xt[idx] = val;
    g_s[(size_t)(s * 1024 + h * 32 + w) * Cdim + c] = val;
}

// ---------------- out = x_after_time + permute(space stream) -------------------
__global__ void final_kernel(float* __restrict__ out) {
    int idx = blockIdx.x * blockDim.x + threadIdx.x;
    if (idx >= Cdim * Dn * Hn * Wn) return;
    int w = idx & 31;
    int t1 = idx >> 5;
    int h = t1 & 31;
    int t2 = t1 >> 5;
    int s = t2 & 7;
    int c = t2 >> 3;
    out[idx] = g_xt[idx] + g_s[(size_t)(s * 1024 + h * 32 + w) * Cdim + c];
}

extern "C" void kernel_launch(void* const* d_in, const int* in_sizes, int n_in,
                              void* d_out, int out_size) {
    const float* x        = (const float*)d_in[0];
    const float* pos_emb  = (const float*)d_in[1];
    const float* t_ln1_g  = (const float*)d_in[2];
    const float* t_ln1_b  = (const float*)d_in[3];
    const float* t_qkv_w  = (const float*)d_in[4];
    const float* t_out_w  = (const float*)d_in[5];
    const float* t_out_b  = (const float*)d_in[6];
    const float* t_ln2_g  = (const float*)d_in[7];
    const float* t_ln2_b  = (const float*)d_in[8];
    const float* t_fc1_w  = (const float*)d_in[9];
    const float* t_fc1_b  = (const float*)d_in[10];
    const float* t_fc2_w  = (const float*)d_in[11];
    const float* t_fc2_b  = (const float*)d_in[12];
    const float* t_lnf_g  = (const float*)d_in[13];
    const float* t_lnf_b  = (const float*)d_in[14];
    const float* s_ln1_g  = (const float*)d_in[15];
    const float* s_ln1_b  = (const float*)d_in[16];
    const float* s_qkv_w  = (const float*)d_in[17];
    const float* s_qkv_b  = (const float*)d_in[18];
    const float* s_rpb    = (const float*)d_in[19];
    const float* s_proj_w = (const float*)d_in[20];
    const float* s_proj_b = (const float*)d_in[21];
    const float* s_ln2_g  = (const float*)d_in[22];
    const float* s_ln2_b  = (const float*)d_in[23];
    const float* s_fc1_w  = (const float*)d_in[24];
    const float* s_fc1_b  = (const float*)d_in[25];
    const float* s_fc2_w  = (const float*)d_in[26];
    const float* s_fc2_b  = (const float*)d_in[27];
    float* out = (float*)d_out;

    float *p_t, *p_y, *p_qkv, *p_s;
    bf16 *p_yb, *p_ob, *p_hidb, *p_wb;
    cudaGetSymbolAddress((void**)&p_t, g_t);
    cudaGetSymbolAddress((void**)&p_y, g_y);
    cudaGetSymbolAddress((void**)&p_qkv, g_qkv);
    cudaGetSymbolAddress((void**)&p_s, g_s);
    cudaGetSymbolAddress((void**)&p_yb, g_yb);
    cudaGetSymbolAddress((void**)&p_ob, g_ob);
    cudaGetSymbolAddress((void**)&p_hidb, g_hidb);
    cudaGetSymbolAddress((void**)&p_wb, g_wb);

    const int NEL = Cdim * Dn * Hn * Wn;

    convert_weights<<<884736 / 256, 256>>>(t_qkv_w, t_out_w, t_fc1_w, t_fc2_w,
                                           s_qkv_w, s_proj_w, s_fc1_w, s_fc2_w);
    build_t_kernel<<<(NTOK * Cdim + 255) / 256, 256>>>(x, pos_emb);

    // ======== time transformer ========
    ln_kernel<<<NTOK / 8, 256>>>(p_t, t_ln1_g, t_ln1_b, nullptr, p_yb);
    gemm_bf16<<<dim3(9, 64), 256>>>(p_yb, p_wb + OFF_TQKV, nullptr, nullptr,
                                    p_qkv, nullptr, NTOK, 576, Cdim, 0);
    time_attn_kernel<<<1024, 192>>>();
    gemm_bf16_s<<<dim3(3, 128), 128>>>(p_ob, p_wb + OFF_TOUT, t_out_b, p_t,
                                       p_t, nullptr, NTOK, Cdim, Cdim, 0);
    ln_kernel<<<NTOK / 8, 256>>>(p_t, t_ln2_g, t_ln2_b, nullptr, p_yb);
    gemm_bf16<<<dim3(12, 64), 256>>>(p_yb, p_wb + OFF_TFC1, t_fc1_b, nullptr,
                                     nullptr, p_hidb, NTOK, HIDN, Cdim, 1);
    gemm_bf16_s<<<dim3(3, 128), 128>>>(p_hidb, p_wb + OFF_TFC2, t_fc2_b, p_t,
                                       p_t, nullptr, NTOK, Cdim, HIDN, 0);
    ln_kernel<<<NTOK / 8, 256>>>(p_t, t_lnf_g, t_lnf_b, p_y, nullptr);
    add_time_kernel<<<(NEL + 255) / 256, 256>>>(x);

    // ======== space transformer (NAT) ========
    ln_kernel<<<NTOK / 8, 256>>>(p_s, s_ln1_g, s_ln1_b, nullptr, p_yb);
    gemm_bf16<<<dim3(9, 64), 256>>>(p_yb, p_wb + OFF_SQKV, s_qkv_b, nullptr,
                                    p_qkv, nullptr, NTOK, 576, Cdim, 0);
    nat_attn_kernel<<<256, 192>>>(s_rpb);
    gemm_bf16_s<<<dim3(3, 128), 128>>>(p_ob, p_wb + OFF_SPROJ, s_proj_b, p_s,
                                       p_s, nullptr, NTOK, Cdim, Cdim, 0);
    ln_kernel<<<NTOK / 8, 256>>>(p_s, s_ln2_g, s_ln2_b, nullptr, p_yb);
    gemm_bf16<<<dim3(12, 64), 256>>>(p_yb, p_wb + OFF_SFC1, s_fc1_b, nullptr,
                                     nullptr, p_hidb, NTOK, HIDN, Cdim, 1);
    gemm_bf16_s<<<dim3(3, 128), 128>>>(p_hidb, p_wb + OFF_SFC2, s_fc2_b, p_s,
                                       p_s, nullptr, NTOK, Cdim, HIDN, 0);
    final_kernel<<<(NEL + 255) / 256, 256>>>(out);
}

// round 8
// speedup vs baseline: 2.0900x; 1.1199x over previous
#include <cuda_runtime.h>
#include <cuda_bf16.h>
#include <stdint.h>
#include <math.h>

#define Cdim 192
#define Dn 8
#define Hn 32
#define Wn 32
#define NHEAD 6
#define HDIM 32
#define HIDN 768
#define NTOK 8192
#define SCALE 0.17677669529663687f

typedef __nv_bfloat16 bf16;

// ---------------- scratch ----------------
__device__ float g_t[NTOK * Cdim];
__device__ float g_y[NTOK * Cdim];
__device__ float g_qkv[NTOK * 3 * Cdim];
__device__ float g_xt[Cdim * Dn * Hn * Wn];
__device__ float g_s[NTOK * Cdim];
__device__ bf16  g_yb[NTOK * Cdim];
__device__ bf16  g_ob[NTOK * Cdim];
__device__ bf16  g_hidb[NTOK * HIDN];
__device__ bf16  g_wb[884736];

#define OFF_TQKV 0
#define OFF_TOUT 110592
#define OFF_TFC1 147456
#define OFF_TFC2 294912
#define OFF_SQKV 442368
#define OFF_SPROJ 552960
#define OFF_SFC1 589824
#define OFF_SFC2 737280

__device__ __forceinline__ float warp_sum(float v) {
#pragma unroll
    for (int o = 16; o > 0; o >>= 1) v += __shfl_xor_sync(0xffffffffu, v, o);
    return v;
}

__device__ __forceinline__ void cp16(void* dst, const void* src) {
    unsigned d = (unsigned)__cvta_generic_to_shared(dst);
    asm volatile("cp.async.cg.shared.global [%0], [%1], 16;" :: "r"(d), "l"(src));
}

__device__ __forceinline__ float gelu_f(float v) {
    return 0.5f * v * (1.0f + erff(v * 0.7071067811865476f));
}

// ---------------- weight conversion ----------------
__global__ void convert_weights(const float* __restrict__ a0, const float* __restrict__ a1,
                                const float* __restrict__ a2, const float* __restrict__ a3,
                                const float* __restrict__ a4, const float* __restrict__ a5,
                                const float* __restrict__ a6, const float* __restrict__ a7) {
    int i = blockIdx.x * blockDim.x + threadIdx.x;
    const float* src; int off;
    if      (i < 110592) { src = a0; off = 0; }
    else if (i < 147456) { src = a1; off = 110592; }
    else if (i < 294912) { src = a2; off = 147456; }
    else if (i < 442368) { src = a3; off = 294912; }
    else if (i < 552960) { src = a4; off = 442368; }
    else if (i < 589824) { src = a5; off = 552960; }
    else if (i < 737280) { src = a6; off = 589824; }
    else                 { src = a7; off = 737280; }
    g_wb[i] = __float2bfloat16(src[i - off]);
}

// ---------------- build t = permute(x) + pos_emb (tiled transpose) -------------
// grid (8, 6, 32), block (32, 8)
__global__ void build_t_kernel(const float* __restrict__ x, const float* __restrict__ pe) {
    __shared__ float sm[32][33];
    int s = blockIdx.x;
    int c0 = blockIdx.y * 32, hw0 = blockIdx.z * 32;
    int tx = threadIdx.x, ty = threadIdx.y;
#pragma unroll
    for (int i = 0; i < 4; i++) {
        int cl = ty + 8 * i;
        sm[cl][tx] = x[((size_t)(c0 + cl) * 8 + s) * 1024 + hw0 + tx];
    }
    __syncthreads();
#pragma unroll
    for (int i = 0; i < 4; i++) {
        int hwl = ty + 8 * i;
        int r = (hw0 + hwl) * 8 + s;
        g_t[(size_t)r * Cdim + c0 + tx] = sm[tx][hwl] + pe[s * Cdim + c0 + tx];
    }
}

// ---------------- LayerNorm ----------------
__global__ void ln_kernel(const float* __restrict__ in, const float* __restrict__ g,
                          const float* __restrict__ b, float* __restrict__ outf,
                          bf16* __restrict__ outb) {
    int warp = threadIdx.x >> 5, lane = threadIdx.x & 31;
    int r = blockIdx.x * 8 + warp;
    const float* row = in + (size_t)r * Cdim;
    float v[6];
    float s = 0.f;
#pragma unroll
    for (int i = 0; i < 6; i++) { v[i] = row[lane + 32 * i]; s += v[i]; }
    s = warp_sum(s);
    float m = s * (1.0f / Cdim);
    float var = 0.f;
#pragma unroll
    for (int i = 0; i < 6; i++) { float d = v[i] - m; var += d * d; }
    var = warp_sum(var) * (1.0f / Cdim);
    float rstd = rsqrtf(var + 1e-5f);
#pragma unroll
    for (int i = 0; i < 6; i++) {
        int c = lane + 32 * i;
        float o = (v[i] - m) * rstd * g[c] + b[c];
        if (outf) outf[(size_t)r * Cdim + c] = o;
        if (outb) outb[(size_t)r * Cdim + c] = __float2bfloat16(o);
    }
}

#define AST 40
#define BST 72

// ============ wide GEMM: BM=128, BN=64, BK=32, 3-stage ring, reg-pipelined ======
#define A_TILE (128 * AST)
#define B_TILE (32 * BST)
__global__ __launch_bounds__(256) void gemm_bf16(
    const bf16* __restrict__ A, const bf16* __restrict__ B,
    const float* __restrict__ bias, const float* __restrict__ res,
    float* __restrict__ outf, bf16* __restrict__ outb,
    int M, int N, int K, int act) {
    __shared__ bf16 As[3][A_TILE];
    __shared__ bf16 Bs[3][B_TILE];
    const int tid = threadIdx.x;
    const int lane = tid & 31;
    const int wid = tid >> 5;
    const int wm = wid >> 1, wn = wid & 1;
    const int row0 = blockIdx.y * 128, col0 = blockIdx.x * 64;
    const int gq = lane >> 2, tq = lane & 3;

    const int lrow8 = (lane & 7) + 8 * ((lane >> 3) & 1);
    const int lcol8 = 8 * (lane >> 4);
    unsigned as_base = (unsigned)__cvta_generic_to_shared(&As[0][0]);
    unsigned bs_base = (unsigned)__cvta_generic_to_shared(&Bs[0][0]);

    float acc[2][4][4] = {};

    const int a_m = (tid >> 2), a_q = (tid & 3);
    const int b_k = (tid >> 3), b_q = (tid & 7);

    auto load_tile = [&](int buf, int k0) {
#pragma unroll
        for (int j = 0; j < 2; j++) {
            int m = a_m + j * 64;
            cp16(&As[buf][m * AST + a_q * 8], &A[(size_t)(row0 + m) * K + k0 + a_q * 8]);
        }
        cp16(&Bs[buf][b_k * BST + b_q * 8], &B[(size_t)(k0 + b_k) * N + col0 + b_q * 8]);
        asm volatile("cp.async.commit_group;");
    };

    unsigned af[2][2][4], bfr[2][4][2];
    auto load_frag = [&](int pb, unsigned abuf, unsigned bbuf, int ks) {
#pragma unroll
        for (int i = 0; i < 2; i++) {
            unsigned addr = abuf + (unsigned)(((wm * 32 + i * 16 + lrow8) * AST + ks + lcol8) * 2);
            asm volatile("ldmatrix.sync.aligned.m8n8.x4.shared.b16 {%0,%1,%2,%3}, [%4];"
                         : "=r"(af[pb][i][0]), "=r"(af[pb][i][1]),
                           "=r"(af[pb][i][2]), "=r"(af[pb][i][3])
                         : "r"(addr));
        }
#pragma unroll
        for (int jp = 0; jp < 2; jp++) {
            unsigned addr = bbuf + (unsigned)(((ks + lrow8) * BST + wn * 32 + jp * 16 + lcol8) * 2);
            asm volatile("ldmatrix.sync.aligned.m8n8.x4.trans.shared.b16 {%0,%1,%2,%3}, [%4];"
                         : "=r"(bfr[pb][jp * 2][0]), "=r"(bfr[pb][jp * 2][1]),
                           "=r"(bfr[pb][jp * 2 + 1][0]), "=r"(bfr[pb][jp * 2 + 1][1])
                         : "r"(addr));
        }
    };

    const int nk = K / 32;
    load_tile(0, 0);
    if (nk > 1) load_tile(1, 32);

    for (int it = 0; it < nk; it++) {
        if (it + 1 < nk) asm volatile("cp.async.wait_group 1;");
        else             asm volatile("cp.async.wait_group 0;");
        __syncthreads();
        if (it + 2 < nk) load_tile((it + 2) % 3, (it + 2) * 32);

        int buf = it % 3;
        unsigned abuf = as_base + buf * (A_TILE * 2);
        unsigned bbuf = bs_base + buf * (B_TILE * 2);
        load_frag(0, abuf, bbuf, 0);
#pragma unroll
        for (int ks = 0; ks < 2; ks++) {
            int pb = ks & 1;
            if (ks < 1) load_frag(pb ^ 1, abuf, bbuf, 16);
#pragma unroll
            for (int i = 0; i < 2; i++)
#pragma unroll
                for (int j = 0; j < 4; j++) {
                    asm volatile(
                        "mma.sync.aligned.m16n8k16.row.col.f32.bf16.bf16.f32 "
                        "{%0,%1,%2,%3}, {%4,%5,%6,%7}, {%8,%9}, {%0,%1,%2,%3};"
                        : "+f"(acc[i][j][0]), "+f"(acc[i][j][1]),
                          "+f"(acc[i][j][2]), "+f"(acc[i][j][3])
                        : "r"(af[pb][i][0]), "r"(af[pb][i][1]),
                          "r"(af[pb][i][2]), "r"(af[pb][i][3]),
                          "r"(bfr[pb][j][0]), "r"(bfr[pb][j][1]));
                }
        }
    }

#pragma unroll
    for (int i = 0; i < 2; i++) {
        int r = row0 + wm * 32 + i * 16 + gq;
#pragma unroll
        for (int j = 0; j < 4; j++) {
            int c = col0 + wn * 32 + j * 8 + 2 * tq;
            float v0 = acc[i][j][0], v1 = acc[i][j][1];
            float v2 = acc[i][j][2], v3 = acc[i][j][3];
            if (bias) {
                float b0 = bias[c], b1 = bias[c + 1];
                v0 += b0; v1 += b1; v2 += b0; v3 += b1;
            }
            if (act) { v0 = gelu_f(v0); v1 = gelu_f(v1); v2 = gelu_f(v2); v3 = gelu_f(v3); }
            if (res) {
                v0 += res[(size_t)r * N + c];
                v1 += res[(size_t)r * N + c + 1];
                v2 += res[(size_t)(r + 8) * N + c];
                v3 += res[(size_t)(r + 8) * N + c + 1];
            }
            if (outf) {
                outf[(size_t)r * N + c]           = v0;
                outf[(size_t)r * N + c + 1]       = v1;
                outf[(size_t)(r + 8) * N + c]     = v2;
                outf[(size_t)(r + 8) * N + c + 1] = v3;
            }
            if (outb) {
                outb[(size_t)r * N + c]           = __float2bfloat16(v0);
                outb[(size_t)r * N + c + 1]       = __float2bfloat16(v1);
                outb[(size_t)(r + 8) * N + c]     = __float2bfloat16(v2);
                outb[(size_t)(r + 8) * N + c + 1] = __float2bfloat16(v3);
            }
        }
    }
}

// ============ skinny GEMM: BM=64, BN=64, BK=32, 4 warps (for N=192 GEMMs) =======
#define A_TILE_S (64 * AST)
#define B_TILE_S (32 * BST)
__global__ __launch_bounds__(128) void gemm_bf16_s(
    const bf16* __restrict__ A, const bf16* __restrict__ B,
    const float* __restrict__ bias, const float* __restrict__ res,
    float* __restrict__ outf, bf16* __restrict__ outb,
    int M, int N, int K, int act) {
    __shared__ bf16 As[3][A_TILE_S];
    __shared__ bf16 Bs[3][B_TILE_S];
    const int tid = threadIdx.x;
    const int lane = tid & 31;
    const int wid = tid >> 5;
    const int wm = wid >> 1, wn = wid & 1;
    const int row0 = blockIdx.y * 64, col0 = blockIdx.x * 64;
    const int gq = lane >> 2, tq = lane & 3;

    const int lrow8 = (lane & 7) + 8 * ((lane >> 3) & 1);
    const int lcol8 = 8 * (lane >> 4);
    unsigned as_base = (unsigned)__cvta_generic_to_shared(&As[0][0]);
    unsigned bs_base = (unsigned)__cvta_generic_to_shared(&Bs[0][0]);

    float acc[2][4][4] = {};

    const int a_m = (tid >> 2), a_q = (tid & 3);
    const int b_k = (tid >> 3), b_q = (tid & 7);

    auto load_tile = [&](int buf, int k0) {
#pragma unroll
        for (int j = 0; j < 2; j++) {
            int m = a_m + j * 32;
            cp16(&As[buf][m * AST + a_q * 8], &A[(size_t)(row0 + m) * K + k0 + a_q * 8]);
        }
#pragma unroll
        for (int j = 0; j < 2; j++) {
            int kr = b_k + j * 16;
            cp16(&Bs[buf][kr * BST + b_q * 8], &B[(size_t)(k0 + kr) * N + col0 + b_q * 8]);
        }
        asm volatile("cp.async.commit_group;");
    };

    unsigned af[2][2][4], bfr[2][4][2];
    auto load_frag = [&](int pb, unsigned abuf, unsigned bbuf, int ks) {
#pragma unroll
        for (int i = 0; i < 2; i++) {
            unsigned addr = abuf + (unsigned)(((wm * 32 + i * 16 + lrow8) * AST + ks + lcol8) * 2);
            asm volatile("ldmatrix.sync.aligned.m8n8.x4.shared.b16 {%0,%1,%2,%3}, [%4];"
                         : "=r"(af[pb][i][0]), "=r"(af[pb][i][1]),
                           "=r"(af[pb][i][2]), "=r"(af[pb][i][3])
                         : "r"(addr));
        }
#pragma unroll
        for (int jp = 0; jp < 2; jp++) {
            unsigned addr = bbuf + (unsigned)(((ks + lrow8) * BST + wn * 32 + jp * 16 + lcol8) * 2);
            asm volatile("ldmatrix.sync.aligned.m8n8.x4.trans.shared.b16 {%0,%1,%2,%3}, [%4];"
                         : "=r"(bfr[pb][jp * 2][0]), "=r"(bfr[pb][jp * 2][1]),
                           "=r"(bfr[pb][jp * 2 + 1][0]), "=r"(bfr[pb][jp * 2 + 1][1])
                         : "r"(addr));
        }
    };

    const int nk = K / 32;
    load_tile(0, 0);
    if (nk > 1) load_tile(1, 32);

    for (int it = 0; it < nk; it++) {
        if (it + 1 < nk) asm volatile("cp.async.wait_group 1;");
        else             asm volatile("cp.async.wait_group 0;");
        __syncthreads();
        if (it + 2 < nk) load_tile((it + 2) % 3, (it + 2) * 32);

        int buf = it % 3;
        unsigned abuf = as_base + buf * (A_TILE_S * 2);
        unsigned bbuf = bs_base + buf * (B_TILE_S * 2);
        load_frag(0, abuf, bbuf, 0);
#pragma unroll
        for (int ks = 0; ks < 2; ks++) {
            int pb = ks & 1;
            if (ks < 1) load_frag(pb ^ 1, abuf, bbuf, 16);
#pragma unroll
            for (int i = 0; i < 2; i++)
#pragma unroll
                for (int j = 0; j < 4; j++) {
                    asm volatile(
                        "mma.sync.aligned.m16n8k16.row.col.f32.bf16.bf16.f32 "
                        "{%0,%1,%2,%3}, {%4,%5,%6,%7}, {%8,%9}, {%0,%1,%2,%3};"
                        : "+f"(acc[i][j][0]), "+f"(acc[i][j][1]),
                          "+f"(acc[i][j][2]), "+f"(acc[i][j][3])
                        : "r"(af[pb][i][0]), "r"(af[pb][i][1]),
                          "r"(af[pb][i][2]), "r"(af[pb][i][3]),
                          "r"(bfr[pb][j][0]), "r"(bfr[pb][j][1]));
                }
        }
    }

#pragma unroll
    for (int i = 0; i < 2; i++) {
        int r = row0 + wm * 32 + i * 16 + gq;
#pragma unroll
        for (int j = 0; j < 4; j++) {
            int c = col0 + wn * 32 + j * 8 + 2 * tq;
            float v0 = acc[i][j][0], v1 = acc[i][j][1];
            float v2 = acc[i][j][2], v3 = acc[i][j][3];
            if (bias) {
                float b0 = bias[c], b1 = bias[c + 1];
                v0 += b0; v1 += b1; v2 += b0; v3 += b1;
            }
            if (act) { v0 = gelu_f(v0); v1 = gelu_f(v1); v2 = gelu_f(v2); v3 = gelu_f(v3); }
            if (res) {
                v0 += res[(size_t)r * N + c];
                v1 += res[(size_t)r * N + c + 1];
                v2 += res[(size_t)(r + 8) * N + c];
                v3 += res[(size_t)(r + 8) * N + c + 1];
            }
            if (outf) {
                outf[(size_t)r * N + c]           = v0;
                outf[(size_t)r * N + c + 1]       = v1;
                outf[(size_t)(r + 8) * N + c]     = v2;
                outf[(size_t)(r + 8) * N + c + 1] = v3;
            }
            if (outb) {
                outb[(size_t)r * N + c]           = __float2bfloat16(v0);
                outb[(size_t)r * N + c + 1]       = __float2bfloat16(v1);
                outb[(size_t)(r + 8) * N + c]     = __float2bfloat16(v2);
                outb[(size_t)(r + 8) * N + c + 1] = __float2bfloat16(v3);
            }
        }
    }
}

// ---------------- time attention ----------------
__global__ void time_attn_kernel() {
    int n = blockIdx.x;
    int h = threadIdx.x >> 5, lane = threadIdx.x & 31;
    const float* base = g_qkv + (size_t)n * 8 * (3 * Cdim);
    float kreg[8], vreg[8];
#pragma unroll
    for (int j = 0; j < 8; j++) {
        kreg[j] = base[j * 576 + Cdim + h * 32 + lane];
        vreg[j] = base[j * 576 + 2 * Cdim + h * 32 + lane];
    }
#pragma unroll
    for (int s = 0; s < 8; s++) {
        float qv = base[s * 576 + h * 32 + lane];
        float sc[8];
#pragma unroll
        for (int j = 0; j < 8; j++) sc[j] = warp_sum(qv * kreg[j]) * SCALE;
        float mx = sc[0];
#pragma unroll
        for (int j = 1; j < 8; j++) mx = fmaxf(mx, sc[j]);
        float sum = 0.f, o = 0.f;
#pragma unroll
        for (int j = 0; j < 8; j++) {
            float p = __expf(sc[j] - mx);
            sum += p;
            o += p * vreg[j];
        }
        g_ob[(size_t)(n * 8 + s) * Cdim + h * 32 + lane] = __float2bfloat16(o / sum);
    }
}

// ---------------- NAT attention: 12 warps = (head, ww-half) ----------------
__global__ void nat_attn_kernel(const float* __restrict__ rpb) {
    int f = blockIdx.x >> 5;
    int hh = blockIdx.x & 31;
    int wno = threadIdx.x >> 5, lane = threadIdx.x & 31;
    int h = wno % NHEAD, half = wno / NHEAD;
    __shared__ float sc[12][52];
    int sh0 = min(max(hh - 3, 0), 25);
    int ww0 = half * 16;
    for (int ww = ww0; ww < ww0 + 16; ww++) {
        int m = f * 1024 + hh * 32 + ww;
        float qv = g_qkv[(size_t)m * 576 + h * 32 + lane] * SCALE;
        int sw0 = min(max(ww - 3, 0), 25);
#pragma unroll
        for (int a = 0; a < 7; a++) {
            int ia = sh0 + a;
            int rh = ia - hh + 6;
            const float* krow = g_qkv + (size_t)(f * 1024 + ia * 32 + sw0) * 576 + Cdim + h * 32 + lane;
#pragma unroll
            for (int b = 0; b < 7; b++) {
                float d = warp_sum(qv * krow[b * 576]);
                if (lane == 0) {
                    int rw = sw0 + b - ww + 6;
                    sc[wno][a * 7 + b] = d + rpb[h * 169 + rh * 13 + rw];
                }
            }
        }
        __syncwarp();
        float mx = -1e30f;
#pragma unroll
        for (int n2 = 0; n2 < 49; n2++) mx = fmaxf(mx, sc[wno][n2]);
        float sum = 0.f, o = 0.f;
#pragma unroll
        for (int a = 0; a < 7; a++) {
            int ia = sh0 + a;
            const float* vrow = g_qkv + (size_t)(f * 1024 + ia * 32 + sw0) * 576 + 2 * Cdim + h * 32 + lane;
#pragma unroll
            for (int b = 0; b < 7; b++) {
                float p = __expf(sc[wno][a * 7 + b] - mx);
                sum += p;
                o += p * vrow[b * 576];
            }
        }
        g_ob[(size_t)m * Cdim + h * 32 + lane] = __float2bfloat16(o / sum);
        __syncwarp();
    }
}

// ---------------- add_time (tiled): xt = x + y(perm); s = same in space order ---
// grid (8, 6, 32), block (32, 8)
__global__ void add_time_kernel(const float* __restrict__ x) {
    __shared__ float ysm[32][33];
    __shared__ float vsm[32][33];
    int s = blockIdx.x;
    int c0 = blockIdx.y * 32, hw0 = blockIdx.z * 32;
    int tx = threadIdx.x, ty = threadIdx.y;
#pragma unroll
    for (int i = 0; i < 4; i++) {
        int hwl = ty + 8 * i;
        ysm[hwl][tx] = g_y[(size_t)((hw0 + hwl) * 8 + s) * Cdim + c0 + tx];
    }
    __syncthreads();
#pragma unroll
    for (int i = 0; i < 4; i++) {
        int cl = ty + 8 * i;
        size_t xi = ((size_t)(c0 + cl) * 8 + s) * 1024 + hw0 + tx;
        float v = x[xi] + ysm[tx][cl];
        g_xt[xi] = v;
        vsm[cl][tx] = v;
    }
    __syncthreads();
#pragma unroll
    for (int i = 0; i < 4; i++) {
        int hwl = ty + 8 * i;
        g_s[(size_t)(s * 1024 + hw0 + hwl) * Cdim + c0 + tx] = vsm[tx][hwl];
    }
}

// ---------------- final (tiled): out = xt + s(perm) ----------------
// grid (8, 6, 32), block (32, 8)
__global__ void final_kernel(float* __restrict__ out) {
    __shared__ float ssm[32][33];
    int s = blockIdx.x;
    int c0 = blockIdx.y * 32, hw0 = blockIdx.z * 32;
    int tx = threadIdx.x, ty = threadIdx.y;
#pragma unroll
    for (int i = 0; i < 4; i++) {
        int hwl = ty + 8 * i;
        ssm[hwl][tx] = g_s[(size_t)(s * 1024 + hw0 + hwl) * Cdim + c0 + tx];
    }
    __syncthreads();
#pragma unroll
    for (int i = 0; i < 4; i++) {
        int cl = ty + 8 * i;
        size_t xi = ((size_t)(c0 + cl) * 8 + s) * 1024 + hw0 + tx;
        out[xi] = g_xt[xi] + ssm[tx][cl];
    }
}

extern "C" void kernel_launch(void* const* d_in, const int* in_sizes, int n_in,
                              void* d_out, int out_size) {
    const float* x        = (const float*)d_in[0];
    const float* pos_emb  = (const float*)d_in[1];
    const float* t_ln1_g  = (const float*)d_in[2];
    const float* t_ln1_b  = (const float*)d_in[3];
    const float* t_qkv_w  = (const float*)d_in[4];
    const float* t_out_w  = (const float*)d_in[5];
    const float* t_out_b  = (const float*)d_in[6];
    const float* t_ln2_g  = (const float*)d_in[7];
    const float* t_ln2_b  = (const float*)d_in[8];
    const float* t_fc1_w  = (const float*)d_in[9];
    const float* t_fc1_b  = (const float*)d_in[10];
    const float* t_fc2_w  = (const float*)d_in[11];
    const float* t_fc2_b  = (const float*)d_in[12];
    const float* t_lnf_g  = (const float*)d_in[13];
    const float* t_lnf_b  = (const float*)d_in[14];
    const float* s_ln1_g  = (const float*)d_in[15];
    const float* s_ln1_b  = (const float*)d_in[16];
    const float* s_qkv_w  = (const float*)d_in[17];
    const float* s_qkv_b  = (const float*)d_in[18];
    const float* s_rpb    = (const float*)d_in[19];
    const float* s_proj_w = (const float*)d_in[20];
    const float* s_proj_b = (const float*)d_in[21];
    const float* s_ln2_g  = (const float*)d_in[22];
    const float* s_ln2_b  = (const float*)d_in[23];
    const float* s_fc1_w  = (const float*)d_in[24];
    const float* s_fc1_b  = (const float*)d_in[25];
    const float* s_fc2_w  = (const float*)d_in[26];
    const float* s_fc2_b  = (const float*)d_in[27];
    float* out = (float*)d_out;

    float *p_t, *p_y, *p_qkv, *p_s;
    bf16 *p_yb, *p_ob, *p_hidb, *p_wb;
    cudaGetSymbolAddress((void**)&p_t, g_t);
    cudaGetSymbolAddress((void**)&p_y, g_y);
    cudaGetSymbolAddress((void**)&p_qkv, g_qkv);
    cudaGetSymbolAddress((void**)&p_s, g_s);
    cudaGetSymbolAddress((void**)&p_yb, g_yb);
    cudaGetSymbolAddress((void**)&p_ob, g_ob);
    cudaGetSymbolAddress((void**)&p_hidb, g_hidb);
    cudaGetSymbolAddress((void**)&p_wb, g_wb);

    convert_weights<<<884736 / 256, 256>>>(t_qkv_w, t_out_w, t_fc1_w, t_fc2_w,
                                           s_qkv_w, s_proj_w, s_fc1_w, s_fc2_w);
    build_t_kernel<<<dim3(8, 6, 32), dim3(32, 8)>>>(x, pos_emb);

    // ======== time transformer ========
    ln_kernel<<<NTOK / 8, 256>>>(p_t, t_ln1_g, t_ln1_b, nullptr, p_yb);
    gemm_bf16<<<dim3(9, 64), 256>>>(p_yb, p_wb + OFF_TQKV, nullptr, nullptr,
                                    p_qkv, nullptr, NTOK, 576, Cdim, 0);
    time_attn_kernel<<<1024, 192>>>();
    gemm_bf16_s<<<dim3(3, 128), 128>>>(p_ob, p_wb + OFF_TOUT, t_out_b, p_t,
                                       p_t, nullptr, NTOK, Cdim, Cdim, 0);
    ln_kernel<<<NTOK / 8, 256>>>(p_t, t_ln2_g, t_ln2_b, nullptr, p_yb);
    gemm_bf16<<<dim3(12, 64), 256>>>(p_yb, p_wb + OFF_TFC1, t_fc1_b, nullptr,
                                     nullptr, p_hidb, NTOK, HIDN, Cdim, 1);
    gemm_bf16_s<<<dim3(3, 128), 128>>>(p_hidb, p_wb + OFF_TFC2, t_fc2_b, p_t,
                                       p_t, nullptr, NTOK, Cdim, HIDN, 0);
    ln_kernel<<<NTOK / 8, 256>>>(p_t, t_lnf_g, t_lnf_b, p_y, nullptr);
    add_time_kernel<<<dim3(8, 6, 32), dim3(32, 8)>>>(x);

    // ======== space transformer (NAT) ========
    ln_kernel<<<NTOK / 8, 256>>>(p_s, s_ln1_g, s_ln1_b, nullptr, p_yb);
    gemm_bf16<<<dim3(9, 64), 256>>>(p_yb, p_wb + OFF_SQKV, s_qkv_b, nullptr,
                                    p_qkv, nullptr, NTOK, 576, Cdim, 0);
    nat_attn_kernel<<<256, 384>>>(s_rpb);
    gemm_bf16_s<<<dim3(3, 128), 128>>>(p_ob, p_wb + OFF_SPROJ, s_proj_b, p_s,
                                       p_s, nullptr, NTOK, Cdim, Cdim, 0);
    ln_kernel<<<NTOK / 8, 256>>>(p_s, s_ln2_g, s_ln2_b, nullptr, p_yb);
    gemm_bf16<<<dim3(12, 64), 256>>>(p_yb, p_wb + OFF_SFC1, s_fc1_b, nullptr,
                                     nullptr, p_hidb, NTOK, HIDN, Cdim, 1);
    gemm_bf16_s<<<dim3(3, 128), 128>>>(p_hidb, p_wb + OFF_SFC2, s_fc2_b, p_s,
                                       p_s, nullptr, NTOK, Cdim, HIDN, 0);
    final_kernel<<<dim3(8, 6, 32), dim3(32, 8)>>>(out);
}